// round 15
// baseline (speedup 1.0000x reference)
#include <cuda_runtime.h>
#include <cuda_fp16.h>
#include <cstdint>

#define B_  4
#define L_  2048
#define C_  1024
#define H_  16
#define HD_ 64
#define M_  (B_ * L_)
#define CW_ (C_ / 2)

#define MASKED (-1e30f)
#define QSCALE (0.125f * 1.4426950408889634f)   // 1/sqrt(hd) * log2(e)

// ---------------- device scratch (no allocs allowed) ----------------
__device__ uint32_t g_xp [M_ * CW_];
__device__ uint32_t g_wqp[C_ * CW_];
__device__ uint32_t g_wkp[C_ * CW_];
__device__ uint32_t g_wvp[C_ * CW_];
__device__ uint32_t g_wpp[C_ * CW_];
__device__ uint32_t g_qp [M_ * CW_];
__device__ uint32_t g_kp [M_ * CW_];
__device__ uint32_t g_vp [M_ * CW_];
__device__ uint32_t g_yp [M_ * CW_];

// ============================ helpers ============================
__device__ __forceinline__ uint32_t packh2(float lo, float hi) {
    uint32_t r;
    asm("cvt.rn.f16x2.f32 %0, %1, %2;" : "=r"(r) : "f"(hi), "f"(lo));
    return r;
}
__device__ __forceinline__ uint32_t smem_u32(const void* p) {
    uint32_t a;
    asm("{ .reg .u64 t; cvta.to.shared.u64 t, %1; cvt.u32.u64 %0, t; }"
        : "=r"(a) : "l"(p));
    return a;
}
__device__ __forceinline__ void mma_f16(float& c0, float& c1, float& c2, float& c3,
                                        uint32_t a0, uint32_t a1, uint32_t a2, uint32_t a3,
                                        uint32_t b0, uint32_t b1) {
    asm volatile(
        "mma.sync.aligned.m16n8k16.row.col.f32.f16.f16.f32 "
        "{%0,%1,%2,%3}, {%4,%5,%6,%7}, {%8,%9}, {%0,%1,%2,%3};"
        : "+f"(c0), "+f"(c1), "+f"(c2), "+f"(c3)
        : "r"(a0), "r"(a1), "r"(a2), "r"(a3), "r"(b0), "r"(b1));
}
__device__ __forceinline__ void ldm_x4(uint32_t& r0, uint32_t& r1, uint32_t& r2,
                                       uint32_t& r3, uint32_t addr) {
    asm volatile("ldmatrix.sync.aligned.m8n8.x4.shared.b16 {%0,%1,%2,%3}, [%4];"
                 : "=r"(r0), "=r"(r1), "=r"(r2), "=r"(r3) : "r"(addr));
}
__device__ __forceinline__ void ldm_x4_t(uint32_t& r0, uint32_t& r1, uint32_t& r2,
                                         uint32_t& r3, uint32_t addr) {
    asm volatile("ldmatrix.sync.aligned.m8n8.x4.trans.shared.b16 {%0,%1,%2,%3}, [%4];"
                 : "=r"(r0), "=r"(r1), "=r"(r2), "=r"(r3) : "r"(addr));
}
#define CP_ASYNC16(sdst, gsrc) \
    asm volatile("cp.async.cg.shared.global [%0], [%1], 16;" \
                 :: "r"(sdst), "l"(gsrc) : "memory")
#define CP_ASYNC4(sdst, gsrc) \
    asm volatile("cp.async.ca.shared.global [%0], [%1], 4;" \
                 :: "r"(sdst), "l"(gsrc) : "memory")
#define CP_COMMIT()  asm volatile("cp.async.commit_group;" ::: "memory")
#define CP_WAIT0()   asm volatile("cp.async.wait_group 0;" ::: "memory")
#define CP_WAIT1()   asm volatile("cp.async.wait_group 1;" ::: "memory")

// ---------------------------------------------------------------------------
// prepass: pack x + 4 weights (one launch, z selects segment)
// ---------------------------------------------------------------------------
__global__ void pack_all(const float* __restrict__ x,
                         const float* __restrict__ s0, const float* __restrict__ s1,
                         const float* __restrict__ s2, const float* __restrict__ s3,
                         uint32_t* __restrict__ dx,
                         uint32_t* __restrict__ d0, uint32_t* __restrict__ d1,
                         uint32_t* __restrict__ d2, uint32_t* __restrict__ d3)
{
    const int z = blockIdx.y;
    const float* src = (z == 0) ? x : (z == 1) ? s0 : (z == 2) ? s1 : (z == 3) ? s2 : s3;
    uint32_t* dst = (z == 0) ? dx : (z == 1) ? d0 : (z == 2) ? d1 : (z == 3) ? d2 : d3;
    const int nw = (z == 0) ? (M_ * CW_) : (C_ * CW_);
    for (int i = blockIdx.x * blockDim.x + threadIdx.x; i < nw;
         i += gridDim.x * blockDim.x) {
        float2 f = ((const float2*)src)[i];
        dst[i] = packh2(f.x, f.y);
    }
}

// ---------------------------------------------------------------------------
// fp16 GEMM: 128m x 64n block tile (finer tiles -> less wave quantization),
// BK=64, 8 warps (2m x 4n), warp tile 64x16, ldmatrix.x4 fragments,
// 3-stage cp.async pipeline, 2 CTAs/SM, fp32 accumulators.
// ---------------------------------------------------------------------------
#define BM 128
#define BN 64
#define AST 36
#define A_BUF_W (BM * AST)                    // 4608 words
#define B_BUF_W (BN * AST)                    // 2304 words
#define ST_W (A_BUF_W + B_BUF_W)              // 6912 words per stage
#define GEMM_SMEM_BYTES (3 * ST_W * 4)        // 82944

__global__ __launch_bounds__(256, 2) void gemm_h2(
    const uint32_t* __restrict__ Xp,
    const uint32_t* __restrict__ W0, const uint32_t* __restrict__ W1,
    const uint32_t* __restrict__ W2,
    uint32_t* __restrict__ Yq, uint32_t* __restrict__ Yk, uint32_t* __restrict__ Yv,
    float* __restrict__ Yf, int qkv, int Kdim, int Ndim)
{
    const int z = blockIdx.z;
    const uint32_t* W = (z == 0) ? W0 : (z == 1) ? W1 : W2;
    const int KW = Kdim >> 1;

    const int m0 = blockIdx.y * BM;
    const int n0 = blockIdx.x * BN;
    const int tid = threadIdx.x;
    const int wid = tid >> 5;
    const int lane = tid & 31;
    const int wm = wid >> 2;          // 0..1 -> 64 m-rows
    const int wn = wid & 3;           // 0..3 -> 16 n-cols
    const int g = lane >> 2;
    const int t = lane & 3;

    extern __shared__ uint32_t gsm[];
    const uint32_t smemu = smem_u32(gsm);

    const int arow_l = (lane & 7) + ((lane >> 3) & 1) * 8;
    const int acol_l = ((lane >> 4) & 1) * 4;
    const int brow_l = (lane & 7) + ((lane >> 4) & 1) * 8;
    const int bcol_l = ((lane >> 3) & 1) * 4;

    const int srow8 = tid >> 3;       // 0..31
    const int slot  = tid & 7;        // 0..7

    const int NCH = Kdim / 64;

    auto stage = [&](int c, int s) {
        const uint32_t abase = smemu + (uint32_t)(s * ST_W) * 4;
        const uint32_t bbase = abase + (uint32_t)A_BUF_W * 4;
        const int kofs = c * 32 + slot * 4;
#pragma unroll
        for (int p = 0; p < 4; p++) {
            const int r = srow8 + 32 * p;
            CP_ASYNC16(abase + (uint32_t)(r * AST + slot * 4) * 4,
                       Xp + (size_t)(m0 + r) * KW + kofs);
        }
#pragma unroll
        for (int p = 0; p < 2; p++) {
            const int r = srow8 + 32 * p;
            CP_ASYNC16(bbase + (uint32_t)(r * AST + slot * 4) * 4,
                       W + (size_t)(n0 + r) * KW + kofs);
        }
        CP_COMMIT();
    };

    float acc[4][2][4];
#pragma unroll
    for (int i = 0; i < 4; i++)
#pragma unroll
        for (int j = 0; j < 2; j++)
#pragma unroll
            for (int r = 0; r < 4; r++) acc[i][j][r] = 0.f;

    stage(0, 0);
    stage(1, 1);

    int buf = 0, nxt = 2;   // nxt = (c + 2) % 3
    for (int c = 0; c < NCH; c++) {
        if (c + 1 < NCH) CP_WAIT1();
        else             CP_WAIT0();
        __syncthreads();    // chunk c visible CTA-wide; all done reading buf (c-1)
        if (c + 2 < NCH) stage(c + 2, nxt);

        const uint32_t AsU = smemu + (uint32_t)(buf * ST_W) * 4;
        const uint32_t BsU = AsU + (uint32_t)A_BUF_W * 4;

#pragma unroll
        for (int ks = 0; ks < 4; ks++) {
            uint32_t bf[2][2];
            ldm_x4(bf[0][0], bf[0][1], bf[1][0], bf[1][1],
                   BsU + (uint32_t)((wn * 16 + brow_l) * AST + ks * 8 + bcol_l) * 4);
#pragma unroll
            for (int mf = 0; mf < 4; mf++) {
                uint32_t a0, a1, a2, a3;
                ldm_x4(a0, a1, a2, a3,
                       AsU + (uint32_t)((wm * 64 + mf * 16 + arow_l) * AST
                                        + ks * 8 + acol_l) * 4);
#pragma unroll
                for (int nf = 0; nf < 2; nf++)
                    mma_f16(acc[mf][nf][0], acc[mf][nf][1], acc[mf][nf][2], acc[mf][nf][3],
                            a0, a1, a2, a3, bf[nf][0], bf[nf][1]);
            }
        }
        buf = (buf == 2) ? 0 : buf + 1;
        nxt = (nxt == 2) ? 0 : nxt + 1;
    }

    if (qkv) {
        uint32_t* Yp = (z == 0) ? Yq : (z == 1) ? Yk : Yv;
        const float sc = (z == 0) ? QSCALE : 1.f;
        const int NW = Ndim >> 1;
#pragma unroll
        for (int mf = 0; mf < 4; mf++) {
            const size_t r0 = (size_t)(m0 + wm * 64 + mf * 16 + g);
            const size_t r1 = r0 + 8;
#pragma unroll
            for (int nf = 0; nf < 2; nf++) {
                const int wcol = (n0 >> 1) + wn * 8 + nf * 4 + t;
                Yp[r0 * NW + wcol] = packh2(acc[mf][nf][0] * sc, acc[mf][nf][1] * sc);
                Yp[r1 * NW + wcol] = packh2(acc[mf][nf][2] * sc, acc[mf][nf][3] * sc);
            }
        }
    } else {
#pragma unroll
        for (int mf = 0; mf < 4; mf++) {
            const size_t r0 = (size_t)(m0 + wm * 64 + mf * 16 + g);
            const size_t r1 = r0 + 8;
#pragma unroll
            for (int nf = 0; nf < 2; nf++) {
                const int col = n0 + wn * 16 + nf * 8 + t * 2;
                *(float2*)(Yf + r0 * Ndim + col) = make_float2(acc[mf][nf][0], acc[mf][nf][1]);
                *(float2*)(Yf + r1 * Ndim + col) = make_float2(acc[mf][nf][2], acc[mf][nf][3]);
            }
        }
    }
}

// ---------------------------------------------------------------------------
// Flash attention (exact R12 version): fp16 mma, ldmatrix, 3-stage cp.async
// pipeline, float-bias masking, max-free softmax, one __syncthreads per tile.
// ---------------------------------------------------------------------------
#define KVST 36
#define KV_W (64 * KVST)
#define FST_W (2 * KV_W)
#define FL_SMEM_BYTES ((3 * FST_W + 3 * 64) * 4)

__global__ __launch_bounds__(256, 2) void flash_h(
    const uint32_t* __restrict__ Qp, const uint32_t* __restrict__ Kp,
    const uint32_t* __restrict__ Vp, const int* __restrict__ mask,
    uint32_t* __restrict__ Yp)
{
    extern __shared__ uint32_t fsm[];
    const uint32_t smemu = smem_u32(fsm);

    const int tid = threadIdx.x;
    const int wid = tid >> 5;
    const int lane = tid & 31;
    const int g = lane >> 2;
    const int t = lane & 3;
    const int qt = (int)gridDim.x - 1 - (int)blockIdx.x;   // long CTAs first
    const int b = blockIdx.y >> 4;
    const int h = blockIdx.y & 15;
    const int q0 = qt * 128;
    const size_t baseW = ((size_t)b * L_) * CW_ + (size_t)h * (HD_ / 2);

    const int krow_l = (lane & 7) + ((lane >> 4) & 1) * 8;
    const int kcol_l = ((lane >> 3) & 1) * 4;
    const int vrow_l = (lane & 7) + ((lane >> 3) & 1) * 8;
    const int vcol_l = ((lane >> 4) & 1) * 4;

    const int srow = tid >> 2;
    const int swc  = (tid & 3) * 8;

    const int r0 = q0 + wid * 16 + g;
    const uint32_t* qp0 = Qp + baseW + (size_t)r0 * CW_;
    const uint32_t* qp1 = qp0 + (size_t)8 * CW_;
    uint32_t qa[4][4];
#pragma unroll
    for (int ks = 0; ks < 4; ks++) {
        qa[ks][0] = __ldg(qp0 + ks * 8 + t);
        qa[ks][1] = __ldg(qp1 + ks * 8 + t);
        qa[ks][2] = __ldg(qp0 + ks * 8 + t + 4);
        qa[ks][3] = __ldg(qp1 + ks * 8 + t + 4);
    }

    float l0 = 0.f, l1 = 0.f;
    float o[8][4];
#pragma unroll
    for (int nf = 0; nf < 8; nf++)
#pragma unroll
        for (int j = 0; j < 4; j++) o[nf][j] = 0.f;

    const int nkt = 2 * (qt + 1);

    auto stage = [&](int kt, int s) {
        const int k0 = kt * 64;
        const uint32_t kdst = smemu + (uint32_t)(s * FST_W + srow * KVST + swc) * 4;
        const uint32_t* ksrc = Kp + baseW + (size_t)(k0 + srow) * CW_ + swc;
        CP_ASYNC16(kdst, ksrc);
        CP_ASYNC16(kdst + 16, ksrc + 4);
        const uint32_t vdst = kdst + (uint32_t)KV_W * 4;
        const uint32_t* vsrc = Vp + baseW + (size_t)(k0 + srow) * CW_ + swc;
        CP_ASYNC16(vdst, vsrc);
        CP_ASYNC16(vdst + 16, vsrc + 4);
        if (tid < 64)
            CP_ASYNC4(smemu + (uint32_t)(3 * FST_W + s * 64 + tid) * 4,
                      mask + b * L_ + k0 + tid);
        CP_COMMIT();
    };

    stage(0, 0);
    if (nkt > 1) stage(1, 1);

    int buf = 0, nxt = 2;
    for (int kt = 0; kt < nkt; kt++) {
        const int k0 = kt * 64;

        if (kt + 1 < nkt) CP_WAIT1();
        else              CP_WAIT0();
        if (tid < 64) {
            uint32_t* mw = fsm + 3 * FST_W + buf * 64 + tid;
            int mv = *(int*)mw;
            *(float*)mw = mv ? 0.f : MASKED;
        }
        __syncthreads();
        if (kt + 2 < nkt) stage(kt + 2, nxt);

        const uint32_t KsU = smemu + (uint32_t)(buf * FST_W) * 4;
        const uint32_t VsU = KsU + (uint32_t)KV_W * 4;
        const float* sbias = (const float*)(fsm + 3 * FST_W + buf * 64);

        float s[8][4];
#pragma unroll
        for (int nf = 0; nf < 8; nf++)
#pragma unroll
            for (int j = 0; j < 4; j++) s[nf][j] = 0.f;

#pragma unroll
        for (int ks = 0; ks < 4; ks++) {
#pragma unroll
            for (int j = 0; j < 4; j++) {
                uint32_t k0r, k1r, k2r, k3r;
                ldm_x4(k0r, k1r, k2r, k3r,
                       KsU + (uint32_t)((16 * j + krow_l) * KVST + 8 * ks + kcol_l) * 4);
                mma_f16(s[2 * j][0], s[2 * j][1], s[2 * j][2], s[2 * j][3],
                        qa[ks][0], qa[ks][1], qa[ks][2], qa[ks][3], k0r, k1r);
                mma_f16(s[2 * j + 1][0], s[2 * j + 1][1], s[2 * j + 1][2], s[2 * j + 1][3],
                        qa[ks][0], qa[ks][1], qa[ks][2], qa[ks][3], k2r, k3r);
            }
        }

#pragma unroll
        for (int nf = 0; nf < 8; nf++) {
            const float b0 = sbias[nf * 8 + 2 * t];
            const float b1 = sbias[nf * 8 + 2 * t + 1];
            s[nf][0] += b0; s[nf][1] += b1;
            s[nf][2] += b0; s[nf][3] += b1;
        }
        if (k0 + 64 > q0) {
#pragma unroll
            for (int nf = 0; nf < 8; nf++) {
                const int kg0 = k0 + nf * 8 + 2 * t;
                const int kg1 = kg0 + 1;
                if (kg0 > r0)     s[nf][0] = MASKED;
                if (kg1 > r0)     s[nf][1] = MASKED;
                if (kg0 > r0 + 8) s[nf][2] = MASKED;
                if (kg1 > r0 + 8) s[nf][3] = MASKED;
            }
        }

        uint32_t P0[8], P1[8];
#pragma unroll
        for (int nf = 0; nf < 8; nf++) {
            float p00 = exp2f(s[nf][0]);
            float p01 = exp2f(s[nf][1]);
            float p10 = exp2f(s[nf][2]);
            float p11 = exp2f(s[nf][3]);
            P0[nf] = packh2(p00, p01);
            P1[nf] = packh2(p10, p11);
            l0 += p00 + p01;
            l1 += p10 + p11;
        }

#pragma unroll
        for (int ks = 0; ks < 4; ks++) {
            const uint32_t a0 = P0[2 * ks];
            const uint32_t a1 = P1[2 * ks];
            const uint32_t a2 = P0[2 * ks + 1];
            const uint32_t a3 = P1[2 * ks + 1];
#pragma unroll
            for (int j = 0; j < 4; j++) {
                uint32_t v0r, v1r, v2r, v3r;
                ldm_x4_t(v0r, v1r, v2r, v3r,
                         VsU + (uint32_t)((16 * ks + vrow_l) * KVST + 8 * j + vcol_l) * 4);
                mma_f16(o[2 * j][0], o[2 * j][1], o[2 * j][2], o[2 * j][3],
                        a0, a1, a2, a3, v0r, v1r);
                mma_f16(o[2 * j + 1][0], o[2 * j + 1][1], o[2 * j + 1][2], o[2 * j + 1][3],
                        a0, a1, a2, a3, v2r, v3r);
            }
        }

        buf = (buf == 2) ? 0 : buf + 1;
        nxt = (nxt == 2) ? 0 : nxt + 1;
    }

    l0 += __shfl_xor_sync(0xffffffffu, l0, 1);
    l0 += __shfl_xor_sync(0xffffffffu, l0, 2);
    l1 += __shfl_xor_sync(0xffffffffu, l1, 1);
    l1 += __shfl_xor_sync(0xffffffffu, l1, 2);
    const float i0 = (l0 > 0.f) ? (1.f / l0) : 0.f;
    const float i1 = (l1 > 0.f) ? (1.f / l1) : 0.f;
    uint32_t* y0 = Yp + baseW + (size_t)r0 * CW_;
    uint32_t* y1 = y0 + (size_t)8 * CW_;
#pragma unroll
    for (int nf = 0; nf < 8; nf++) {
        y0[nf * 4 + t] = packh2(o[nf][0] * i0, o[nf][1] * i0);
        y1[nf * 4 + t] = packh2(o[nf][2] * i1, o[nf][3] * i1);
    }
}

// ---------------------------------------------------------------------------
// launch
// ---------------------------------------------------------------------------
extern "C" void kernel_launch(void* const* d_in, const int* in_sizes, int n_in,
                              void* d_out, int out_size)
{
    const float* x    = (const float*)d_in[0];
    const float* Wq   = (const float*)d_in[1];
    const float* Wk   = (const float*)d_in[2];
    const float* Wv   = (const float*)d_in[3];
    const float* Wp   = (const float*)d_in[4];
    const int*   mask = (const int*)  d_in[5];
    float*       out  = (float*)d_out;

    uint32_t *xp, *wqp, *wkp, *wvp, *wpp, *qp, *kp, *vp, *yp;
    cudaGetSymbolAddress((void**)&xp,  g_xp);
    cudaGetSymbolAddress((void**)&wqp, g_wqp);
    cudaGetSymbolAddress((void**)&wkp, g_wkp);
    cudaGetSymbolAddress((void**)&wvp, g_wvp);
    cudaGetSymbolAddress((void**)&wpp, g_wpp);
    cudaGetSymbolAddress((void**)&qp,  g_qp);
    cudaGetSymbolAddress((void**)&kp,  g_kp);
    cudaGetSymbolAddress((void**)&vp,  g_vp);
    cudaGetSymbolAddress((void**)&yp,  g_yp);

    cudaFuncSetAttribute(gemm_h2, cudaFuncAttributeMaxDynamicSharedMemorySize,
                         GEMM_SMEM_BYTES);
    cudaFuncSetAttribute(flash_h, cudaFuncAttributeMaxDynamicSharedMemorySize,
                         FL_SMEM_BYTES);

    // prepass: pack x + all weights (one launch)
    dim3 gpk(1024, 5);
    pack_all<<<gpk, 256>>>(x, Wq, Wk, Wv, Wp, xp, wqp, wkp, wvp, wpp);

    // QKV projections
    dim3 gq(C_ / BN, M_ / BM, 3);
    gemm_h2<<<gq, 256, GEMM_SMEM_BYTES>>>(xp, wqp, wkp, wvp, qp, kp, vp,
                                          nullptr, 1, C_, C_);

    // flash attention
    dim3 ga(L_ / 128, B_ * H_);
    flash_h<<<ga, 256, FL_SMEM_BYTES>>>(qp, kp, vp, mask, yp);

    // output projection (fp32 out)
    dim3 gp(C_ / BN, M_ / BM, 1);
    gemm_h2<<<gp, 256, GEMM_SMEM_BYTES>>>(yp, wpp, wpp, wpp, nullptr, nullptr,
                                          nullptr, out, 0, C_, C_);
}

// round 16
// speedup vs baseline: 1.1574x; 1.1574x over previous
#include <cuda_runtime.h>
#include <cuda_fp16.h>
#include <cstdint>

#define B_  4
#define L_  2048
#define C_  1024
#define H_  16
#define HD_ 64
#define M_  (B_ * L_)
#define CW_ (C_ / 2)

#define MASKED (-1e30f)
#define QSCALE (0.125f * 1.4426950408889634f)   // 1/sqrt(hd) * log2(e)

// ---------------- device scratch (no allocs allowed) ----------------
__device__ uint32_t g_xp [M_ * CW_];
__device__ uint32_t g_wqp[C_ * CW_];
__device__ uint32_t g_wkp[C_ * CW_];
__device__ uint32_t g_wvp[C_ * CW_];
__device__ uint32_t g_wpp[C_ * CW_];
__device__ uint32_t g_qp [M_ * CW_];
__device__ uint32_t g_kp [M_ * CW_];
__device__ uint32_t g_vp [M_ * CW_];
__device__ uint32_t g_yp [M_ * CW_];

// ============================ helpers ============================
__device__ __forceinline__ uint32_t packh2(float lo, float hi) {
    uint32_t r;
    asm("cvt.rn.f16x2.f32 %0, %1, %2;" : "=r"(r) : "f"(hi), "f"(lo));
    return r;
}
__device__ __forceinline__ uint32_t smem_u32(const void* p) {
    uint32_t a;
    asm("{ .reg .u64 t; cvta.to.shared.u64 t, %1; cvt.u32.u64 %0, t; }"
        : "=r"(a) : "l"(p));
    return a;
}
__device__ __forceinline__ void mma_f16(float& c0, float& c1, float& c2, float& c3,
                                        uint32_t a0, uint32_t a1, uint32_t a2, uint32_t a3,
                                        uint32_t b0, uint32_t b1) {
    asm volatile(
        "mma.sync.aligned.m16n8k16.row.col.f32.f16.f16.f32 "
        "{%0,%1,%2,%3}, {%4,%5,%6,%7}, {%8,%9}, {%0,%1,%2,%3};"
        : "+f"(c0), "+f"(c1), "+f"(c2), "+f"(c3)
        : "r"(a0), "r"(a1), "r"(a2), "r"(a3), "r"(b0), "r"(b1));
}
__device__ __forceinline__ void ldm_x4(uint32_t& r0, uint32_t& r1, uint32_t& r2,
                                       uint32_t& r3, uint32_t addr) {
    asm volatile("ldmatrix.sync.aligned.m8n8.x4.shared.b16 {%0,%1,%2,%3}, [%4];"
                 : "=r"(r0), "=r"(r1), "=r"(r2), "=r"(r3) : "r"(addr));
}
__device__ __forceinline__ void ldm_x4_t(uint32_t& r0, uint32_t& r1, uint32_t& r2,
                                         uint32_t& r3, uint32_t addr) {
    asm volatile("ldmatrix.sync.aligned.m8n8.x4.trans.shared.b16 {%0,%1,%2,%3}, [%4];"
                 : "=r"(r0), "=r"(r1), "=r"(r2), "=r"(r3) : "r"(addr));
}
#define CP_ASYNC16(sdst, gsrc) \
    asm volatile("cp.async.cg.shared.global [%0], [%1], 16;" \
                 :: "r"(sdst), "l"(gsrc) : "memory")
#define CP_ASYNC4(sdst, gsrc) \
    asm volatile("cp.async.ca.shared.global [%0], [%1], 4;" \
                 :: "r"(sdst), "l"(gsrc) : "memory")
#define CP_COMMIT()  asm volatile("cp.async.commit_group;" ::: "memory")
#define CP_WAIT0()   asm volatile("cp.async.wait_group 0;" ::: "memory")
#define CP_WAIT1()   asm volatile("cp.async.wait_group 1;" ::: "memory")

// ---------------------------------------------------------------------------
// prepass: pack x + 4 weights (one launch, z selects segment)
// ---------------------------------------------------------------------------
__global__ void pack_all(const float* __restrict__ x,
                         const float* __restrict__ s0, const float* __restrict__ s1,
                         const float* __restrict__ s2, const float* __restrict__ s3,
                         uint32_t* __restrict__ dx,
                         uint32_t* __restrict__ d0, uint32_t* __restrict__ d1,
                         uint32_t* __restrict__ d2, uint32_t* __restrict__ d3)
{
    const int z = blockIdx.y;
    const float* src = (z == 0) ? x : (z == 1) ? s0 : (z == 2) ? s1 : (z == 3) ? s2 : s3;
    uint32_t* dst = (z == 0) ? dx : (z == 1) ? d0 : (z == 2) ? d1 : (z == 3) ? d2 : d3;
    const int nw = (z == 0) ? (M_ * CW_) : (C_ * CW_);
    for (int i = blockIdx.x * blockDim.x + threadIdx.x; i < nw;
         i += gridDim.x * blockDim.x) {
        float2 f = ((const float2*)src)[i];
        dst[i] = packh2(f.x, f.y);
    }
}

// ---------------------------------------------------------------------------
// fp16 GEMM (R12 exact): 128m x 128n block, BK=64, 8 warps (2m x 4n),
// warp tile 64x32, ldmatrix.x4, 3-stage cp.async pipeline, 2 CTAs/SM.
// ---------------------------------------------------------------------------
#define BM 128
#define BN 128
#define AST 36
#define A_BUF_W (BM * AST)                    // 4608 words
#define B_BUF_W (BN * AST)                    // 4608 words
#define ST_W (A_BUF_W + B_BUF_W)              // 9216 words per stage
#define GEMM_SMEM_BYTES (3 * ST_W * 4)        // 110592

__global__ __launch_bounds__(256, 2) void gemm_h2(
    const uint32_t* __restrict__ Xp,
    const uint32_t* __restrict__ W0, const uint32_t* __restrict__ W1,
    const uint32_t* __restrict__ W2,
    uint32_t* __restrict__ Yq, uint32_t* __restrict__ Yk, uint32_t* __restrict__ Yv,
    float* __restrict__ Yf, int qkv, int Kdim, int Ndim)
{
    const int z = blockIdx.z;
    const uint32_t* W = (z == 0) ? W0 : (z == 1) ? W1 : W2;
    const int KW = Kdim >> 1;

    const int m0 = blockIdx.y * BM;
    const int n0 = blockIdx.x * BN;
    const int tid = threadIdx.x;
    const int wid = tid >> 5;
    const int lane = tid & 31;
    const int wm = wid >> 2;
    const int wn = wid & 3;
    const int g = lane >> 2;
    const int t = lane & 3;

    extern __shared__ uint32_t gsm[];
    const uint32_t smemu = smem_u32(gsm);

    const int arow_l = (lane & 7) + ((lane >> 3) & 1) * 8;
    const int acol_l = ((lane >> 4) & 1) * 4;
    const int brow_l = (lane & 7) + ((lane >> 4) & 1) * 8;
    const int bcol_l = ((lane >> 3) & 1) * 4;

    const int srow8 = tid >> 3;       // 0..31
    const int slot  = tid & 7;        // 0..7

    const int NCH = Kdim / 64;

    auto stage = [&](int c, int s) {
        const uint32_t abase = smemu + (uint32_t)(s * ST_W) * 4;
        const uint32_t bbase = abase + (uint32_t)A_BUF_W * 4;
        const int kofs = c * 32 + slot * 4;
#pragma unroll
        for (int p = 0; p < 4; p++) {
            const int r = srow8 + 32 * p;
            CP_ASYNC16(abase + (uint32_t)(r * AST + slot * 4) * 4,
                       Xp + (size_t)(m0 + r) * KW + kofs);
            CP_ASYNC16(bbase + (uint32_t)(r * AST + slot * 4) * 4,
                       W + (size_t)(n0 + r) * KW + kofs);
        }
        CP_COMMIT();
    };

    float acc[4][4][4];
#pragma unroll
    for (int i = 0; i < 4; i++)
#pragma unroll
        for (int j = 0; j < 4; j++)
#pragma unroll
            for (int r = 0; r < 4; r++) acc[i][j][r] = 0.f;

    stage(0, 0);
    stage(1, 1);

    int buf = 0, nxt = 2;   // nxt = (c + 2) % 3
    for (int c = 0; c < NCH; c++) {
        if (c + 1 < NCH) CP_WAIT1();
        else             CP_WAIT0();
        __syncthreads();    // chunk c visible CTA-wide; all done reading buf (c-1)
        if (c + 2 < NCH) stage(c + 2, nxt);

        const uint32_t AsU = smemu + (uint32_t)(buf * ST_W) * 4;
        const uint32_t BsU = AsU + (uint32_t)A_BUF_W * 4;

#pragma unroll
        for (int ks = 0; ks < 4; ks++) {
            uint32_t bf[4][2];
#pragma unroll
            for (int j = 0; j < 2; j++) {
                ldm_x4(bf[2 * j][0], bf[2 * j][1], bf[2 * j + 1][0], bf[2 * j + 1][1],
                       BsU + (uint32_t)((wn * 32 + 16 * j + brow_l) * AST
                                        + ks * 8 + bcol_l) * 4);
            }
#pragma unroll
            for (int mf = 0; mf < 4; mf++) {
                uint32_t a0, a1, a2, a3;
                ldm_x4(a0, a1, a2, a3,
                       AsU + (uint32_t)((wm * 64 + mf * 16 + arow_l) * AST
                                        + ks * 8 + acol_l) * 4);
#pragma unroll
                for (int nf = 0; nf < 4; nf++)
                    mma_f16(acc[mf][nf][0], acc[mf][nf][1], acc[mf][nf][2], acc[mf][nf][3],
                            a0, a1, a2, a3, bf[nf][0], bf[nf][1]);
            }
        }
        buf = (buf == 2) ? 0 : buf + 1;
        nxt = (nxt == 2) ? 0 : nxt + 1;
    }

    if (qkv) {
        uint32_t* Yp = (z == 0) ? Yq : (z == 1) ? Yk : Yv;
        const float sc = (z == 0) ? QSCALE : 1.f;
        const int NW = Ndim >> 1;
#pragma unroll
        for (int mf = 0; mf < 4; mf++) {
            const size_t r0 = (size_t)(m0 + wm * 64 + mf * 16 + g);
            const size_t r1 = r0 + 8;
#pragma unroll
            for (int nf = 0; nf < 4; nf++) {
                const int wcol = (n0 >> 1) + wn * 16 + nf * 4 + t;
                Yp[r0 * NW + wcol] = packh2(acc[mf][nf][0] * sc, acc[mf][nf][1] * sc);
                Yp[r1 * NW + wcol] = packh2(acc[mf][nf][2] * sc, acc[mf][nf][3] * sc);
            }
        }
    } else {
#pragma unroll
        for (int mf = 0; mf < 4; mf++) {
            const size_t r0 = (size_t)(m0 + wm * 64 + mf * 16 + g);
            const size_t r1 = r0 + 8;
#pragma unroll
            for (int nf = 0; nf < 4; nf++) {
                const int col = n0 + wn * 32 + nf * 8 + t * 2;
                *(float2*)(Yf + r0 * Ndim + col) = make_float2(acc[mf][nf][0], acc[mf][nf][1]);
                *(float2*)(Yf + r1 * Ndim + col) = make_float2(acc[mf][nf][2], acc[mf][nf][3]);
            }
        }
    }
}

// ---------------------------------------------------------------------------
// Flash attention (R12 + last-tile warp skip): fp16 mma, ldmatrix, 3-stage
// cp.async pipeline, float-bias masking, max-free softmax. On the final key
// tile (k0 = q0+64), warps 0-3 own q-rows entirely below every key ->
// fully masked -> their whole compute block contributes 0 to l and O and is
// skipped with ONE warp-uniform branch (hot path untouched).
// ---------------------------------------------------------------------------
#define KVST 36
#define KV_W (64 * KVST)
#define FST_W (2 * KV_W)
#define FL_SMEM_BYTES ((3 * FST_W + 3 * 64) * 4)

__global__ __launch_bounds__(256, 2) void flash_h(
    const uint32_t* __restrict__ Qp, const uint32_t* __restrict__ Kp,
    const uint32_t* __restrict__ Vp, const int* __restrict__ mask,
    uint32_t* __restrict__ Yp)
{
    extern __shared__ uint32_t fsm[];
    const uint32_t smemu = smem_u32(fsm);

    const int tid = threadIdx.x;
    const int wid = tid >> 5;
    const int lane = tid & 31;
    const int g = lane >> 2;
    const int t = lane & 3;
    const int qt = (int)gridDim.x - 1 - (int)blockIdx.x;   // long CTAs first
    const int b = blockIdx.y >> 4;
    const int h = blockIdx.y & 15;
    const int q0 = qt * 128;
    const size_t baseW = ((size_t)b * L_) * CW_ + (size_t)h * (HD_ / 2);

    const int krow_l = (lane & 7) + ((lane >> 4) & 1) * 8;
    const int kcol_l = ((lane >> 3) & 1) * 4;
    const int vrow_l = (lane & 7) + ((lane >> 3) & 1) * 8;
    const int vcol_l = ((lane >> 4) & 1) * 4;

    const int srow = tid >> 2;
    const int swc  = (tid & 3) * 8;

    const int r0 = q0 + wid * 16 + g;
    const uint32_t* qp0 = Qp + baseW + (size_t)r0 * CW_;
    const uint32_t* qp1 = qp0 + (size_t)8 * CW_;
    uint32_t qa[4][4];
#pragma unroll
    for (int ks = 0; ks < 4; ks++) {
        qa[ks][0] = __ldg(qp0 + ks * 8 + t);
        qa[ks][1] = __ldg(qp1 + ks * 8 + t);
        qa[ks][2] = __ldg(qp0 + ks * 8 + t + 4);
        qa[ks][3] = __ldg(qp1 + ks * 8 + t + 4);
    }

    float l0 = 0.f, l1 = 0.f;
    float o[8][4];
#pragma unroll
    for (int nf = 0; nf < 8; nf++)
#pragma unroll
        for (int j = 0; j < 4; j++) o[nf][j] = 0.f;

    const int nkt = 2 * (qt + 1);

    auto stage = [&](int kt, int s) {
        const int k0 = kt * 64;
        const uint32_t kdst = smemu + (uint32_t)(s * FST_W + srow * KVST + swc) * 4;
        const uint32_t* ksrc = Kp + baseW + (size_t)(k0 + srow) * CW_ + swc;
        CP_ASYNC16(kdst, ksrc);
        CP_ASYNC16(kdst + 16, ksrc + 4);
        const uint32_t vdst = kdst + (uint32_t)KV_W * 4;
        const uint32_t* vsrc = Vp + baseW + (size_t)(k0 + srow) * CW_ + swc;
        CP_ASYNC16(vdst, vsrc);
        CP_ASYNC16(vdst + 16, vsrc + 4);
        if (tid < 64)
            CP_ASYNC4(smemu + (uint32_t)(3 * FST_W + s * 64 + tid) * 4,
                      mask + b * L_ + k0 + tid);
        CP_COMMIT();
    };

    stage(0, 0);
    if (nkt > 1) stage(1, 1);

    int buf = 0, nxt = 2;
    for (int kt = 0; kt < nkt; kt++) {
        const int k0 = kt * 64;

        if (kt + 1 < nkt) CP_WAIT1();
        else              CP_WAIT0();
        if (tid < 64) {
            uint32_t* mw = fsm + 3 * FST_W + buf * 64 + tid;
            int mv = *(int*)mw;
            *(float*)mw = mv ? 0.f : MASKED;
        }
        __syncthreads();
        if (kt + 2 < nkt) stage(kt + 2, nxt);

        // last key tile: warps 0-3 are fully causally masked -> contribute 0
        if (!(kt == nkt - 1 && wid < 4)) {
            const uint32_t KsU = smemu + (uint32_t)(buf * FST_W) * 4;
            const uint32_t VsU = KsU + (uint32_t)KV_W * 4;
            const float* sbias = (const float*)(fsm + 3 * FST_W + buf * 64);

            float s[8][4];
#pragma unroll
            for (int nf = 0; nf < 8; nf++)
#pragma unroll
                for (int j = 0; j < 4; j++) s[nf][j] = 0.f;

#pragma unroll
            for (int ks = 0; ks < 4; ks++) {
#pragma unroll
                for (int j = 0; j < 4; j++) {
                    uint32_t k0r, k1r, k2r, k3r;
                    ldm_x4(k0r, k1r, k2r, k3r,
                           KsU + (uint32_t)((16 * j + krow_l) * KVST + 8 * ks + kcol_l) * 4);
                    mma_f16(s[2 * j][0], s[2 * j][1], s[2 * j][2], s[2 * j][3],
                            qa[ks][0], qa[ks][1], qa[ks][2], qa[ks][3], k0r, k1r);
                    mma_f16(s[2 * j + 1][0], s[2 * j + 1][1], s[2 * j + 1][2], s[2 * j + 1][3],
                            qa[ks][0], qa[ks][1], qa[ks][2], qa[ks][3], k2r, k3r);
                }
            }

#pragma unroll
            for (int nf = 0; nf < 8; nf++) {
                const float b0 = sbias[nf * 8 + 2 * t];
                const float b1 = sbias[nf * 8 + 2 * t + 1];
                s[nf][0] += b0; s[nf][1] += b1;
                s[nf][2] += b0; s[nf][3] += b1;
            }
            if (k0 + 64 > q0) {
#pragma unroll
                for (int nf = 0; nf < 8; nf++) {
                    const int kg0 = k0 + nf * 8 + 2 * t;
                    const int kg1 = kg0 + 1;
                    if (kg0 > r0)     s[nf][0] = MASKED;
                    if (kg1 > r0)     s[nf][1] = MASKED;
                    if (kg0 > r0 + 8) s[nf][2] = MASKED;
                    if (kg1 > r0 + 8) s[nf][3] = MASKED;
                }
            }

            uint32_t P0[8], P1[8];
#pragma unroll
            for (int nf = 0; nf < 8; nf++) {
                float p00 = exp2f(s[nf][0]);
                float p01 = exp2f(s[nf][1]);
                float p10 = exp2f(s[nf][2]);
                float p11 = exp2f(s[nf][3]);
                P0[nf] = packh2(p00, p01);
                P1[nf] = packh2(p10, p11);
                l0 += p00 + p01;
                l1 += p10 + p11;
            }

#pragma unroll
            for (int ks = 0; ks < 4; ks++) {
                const uint32_t a0 = P0[2 * ks];
                const uint32_t a1 = P1[2 * ks];
                const uint32_t a2 = P0[2 * ks + 1];
                const uint32_t a3 = P1[2 * ks + 1];
#pragma unroll
                for (int j = 0; j < 4; j++) {
                    uint32_t v0r, v1r, v2r, v3r;
                    ldm_x4_t(v0r, v1r, v2r, v3r,
                             VsU + (uint32_t)((16 * ks + vrow_l) * KVST + 8 * j + vcol_l) * 4);
                    mma_f16(o[2 * j][0], o[2 * j][1], o[2 * j][2], o[2 * j][3],
                            a0, a1, a2, a3, v0r, v1r);
                    mma_f16(o[2 * j + 1][0], o[2 * j + 1][1], o[2 * j + 1][2], o[2 * j + 1][3],
                            a0, a1, a2, a3, v2r, v3r);
                }
            }
        }

        buf = (buf == 2) ? 0 : buf + 1;
        nxt = (nxt == 2) ? 0 : nxt + 1;
    }

    // epilogue: one cross-lane reduction of l, normalize, store
    l0 += __shfl_xor_sync(0xffffffffu, l0, 1);
    l0 += __shfl_xor_sync(0xffffffffu, l0, 2);
    l1 += __shfl_xor_sync(0xffffffffu, l1, 1);
    l1 += __shfl_xor_sync(0xffffffffu, l1, 2);
    const float i0 = (l0 > 0.f) ? (1.f / l0) : 0.f;
    const float i1 = (l1 > 0.f) ? (1.f / l1) : 0.f;
    uint32_t* y0 = Yp + baseW + (size_t)r0 * CW_;
    uint32_t* y1 = y0 + (size_t)8 * CW_;
#pragma unroll
    for (int nf = 0; nf < 8; nf++) {
        y0[nf * 4 + t] = packh2(o[nf][0] * i0, o[nf][1] * i0);
        y1[nf * 4 + t] = packh2(o[nf][2] * i1, o[nf][3] * i1);
    }
}

// ---------------------------------------------------------------------------
// launch
// ---------------------------------------------------------------------------
extern "C" void kernel_launch(void* const* d_in, const int* in_sizes, int n_in,
                              void* d_out, int out_size)
{
    const float* x    = (const float*)d_in[0];
    const float* Wq   = (const float*)d_in[1];
    const float* Wk   = (const float*)d_in[2];
    const float* Wv   = (const float*)d_in[3];
    const float* Wp   = (const float*)d_in[4];
    const int*   mask = (const int*)  d_in[5];
    float*       out  = (float*)d_out;

    uint32_t *xp, *wqp, *wkp, *wvp, *wpp, *qp, *kp, *vp, *yp;
    cudaGetSymbolAddress((void**)&xp,  g_xp);
    cudaGetSymbolAddress((void**)&wqp, g_wqp);
    cudaGetSymbolAddress((void**)&wkp, g_wkp);
    cudaGetSymbolAddress((void**)&wvp, g_wvp);
    cudaGetSymbolAddress((void**)&wpp, g_wpp);
    cudaGetSymbolAddress((void**)&qp,  g_qp);
    cudaGetSymbolAddress((void**)&kp,  g_kp);
    cudaGetSymbolAddress((void**)&vp,  g_vp);
    cudaGetSymbolAddress((void**)&yp,  g_yp);

    cudaFuncSetAttribute(gemm_h2, cudaFuncAttributeMaxDynamicSharedMemorySize,
                         GEMM_SMEM_BYTES);
    cudaFuncSetAttribute(flash_h, cudaFuncAttributeMaxDynamicSharedMemorySize,
                         FL_SMEM_BYTES);

    // prepass: pack x + all weights (one launch)
    dim3 gpk(1024, 5);
    pack_all<<<gpk, 256>>>(x, Wq, Wk, Wv, Wp, xp, wqp, wkp, wvp, wpp);

    // QKV projections
    dim3 gq(C_ / BN, M_ / BM, 3);
    gemm_h2<<<gq, 256, GEMM_SMEM_BYTES>>>(xp, wqp, wkp, wvp, qp, kp, vp,
                                          nullptr, 1, C_, C_);

    // flash attention
    dim3 ga(L_ / 128, B_ * H_);
    flash_h<<<ga, 256, FL_SMEM_BYTES>>>(qp, kp, vp, mask, yp);

    // output projection (fp32 out)
    dim3 gp(C_ / BN, M_ / BM, 1);
    gemm_h2<<<gp, 256, GEMM_SMEM_BYTES>>>(yp, wpp, wpp, wpp, nullptr, nullptr,
                                          nullptr, out, 0, C_, C_);
}